// round 4
// baseline (speedup 1.0000x reference)
#include <cuda_runtime.h>
#include <cuda_bf16.h>
#include <stdint.h>

// units2indices: 80M fp32 bipolar {-1,+1} -> 8M codebook indices in [0,1024),
// groups of num_bits=10, first element is MSB.
//
// KEY FINDING (R1-R3 post-mortems): the harness's __output__ dtype is
// float32 (rel_err was exactly 1.0 for three different int32-writing
// kernels = int bit patterns read back as float denormals ~ 0).
// So we store the index VALUES as float32.
//
// Bit rule: fp32 +1.0 has sign bit 0 -> bit 1; -1.0 sign bit 1 -> bit 0.
//   bit = 1 - (word >> 31)

__global__ __launch_bounds__(256)
void units2indices_pairs_f32(const uint4* __restrict__ in4,
                             float2* __restrict__ out2,
                             int n_pairs)
{
    int t = blockIdx.x * blockDim.x + threadIdx.x;
    if (t >= n_pairs) return;

    // 5 x uint4 = 20 words = 2 groups of 10
    const uint4* p = in4 + (size_t)t * 5;
    uint4 v0 = p[0], v1 = p[1], v2 = p[2], v3 = p[3], v4 = p[4];

    unsigned w[20] = {
        v0.x, v0.y, v0.z, v0.w,
        v1.x, v1.y, v1.z, v1.w,
        v2.x, v2.y, v2.z, v2.w,
        v3.x, v3.y, v3.z, v3.w,
        v4.x, v4.y, v4.z, v4.w
    };

    int i0 = 0, i1 = 0;
    #pragma unroll
    for (int i = 0; i < 10; i++)
        i0 = (i0 << 1) | (int)(1u - (w[i] >> 31));
    #pragma unroll
    for (int i = 0; i < 10; i++)
        i1 = (i1 << 1) | (int)(1u - (w[10 + i] >> 31));

    out2[t] = make_float2((float)i0, (float)i1);
}

// Generic fallback (num_bits != 10 or odd group count tail).
__global__ __launch_bounds__(256)
void units2indices_generic_f32(const unsigned* __restrict__ in,
                               float* __restrict__ out,
                               int n_groups, int num_bits, int g_start)
{
    int g = g_start + blockIdx.x * blockDim.x + threadIdx.x;
    if (g >= n_groups) return;

    const unsigned* p = in + (size_t)g * num_bits;
    int idx = 0;
    for (int i = 0; i < num_bits; i++)
        idx = (idx << 1) | (int)(1u - (p[i] >> 31));
    out[g] = (float)idx;
}

extern "C" void kernel_launch(void* const* d_in, const int* in_sizes, int n_in,
                              void* d_out, int out_size)
{
    // Input tensor = largest buffer (robust to ordering / scalar inputs).
    int imax = 0;
    for (int i = 1; i < n_in; i++)
        if (in_sizes[i] > in_sizes[imax]) imax = i;

    const unsigned* in = (const unsigned*)d_in[imax];
    float* out = (float*)d_out;

    long long n_total = (long long)in_sizes[imax];
    int num_bits = (out_size > 0) ? (int)(n_total / (long long)out_size) : 10;
    if (num_bits <= 0) num_bits = 10;

    int threads = 256;
    bool aligned16 = (((uintptr_t)in) & 15u) == 0;

    if (num_bits == 10 && aligned16) {
        int n_pairs = out_size / 2;
        if (n_pairs > 0) {
            int blocks = (n_pairs + threads - 1) / threads;
            units2indices_pairs_f32<<<blocks, threads>>>(
                (const uint4*)in, (float2*)out, n_pairs);
        }
        if (out_size & 1) {
            // tail group
            units2indices_generic_f32<<<1, 32>>>(
                in, out, out_size, 10, out_size - 1);
        }
    } else {
        int blocks = (out_size + threads - 1) / threads;
        units2indices_generic_f32<<<blocks, threads>>>(
            in, out, out_size, num_bits, 0);
    }
}